// round 8
// baseline (speedup 1.0000x reference)
#include <cuda_runtime.h>
#include <cuda_bf16.h>
#include <cstdint>
#include <cstddef>

#define T_LEN 4096
#define EMBD  300
#define HID   512
#define KTAG  20
#define START_TAG 18
#define STOP_TAG  19
#define NEGV  (-10000.0f)
#define CHUNK 16
#define NCHUNK (T_LEN / CHUNK)   // 256
#define NREP  4                  // h-broadcast replicas (poll decongestion)
#define HPAD  768                // replica stride in u64 (512 + 2KB pad)

// ---------------- scratch (static device globals; no allocation) ----------------
__device__ float              g_xproj[2][T_LEN][4 * HID];  // 64 MB
__device__ float              g_hs[2][T_LEN][HID];         // 16 MB
__device__ float              g_feats[T_LEN][KTAG];
__device__ __align__(16) unsigned long long g_hrep[2][2][NREP][HPAD]; // [dir][parity][rep][h]
__device__ float              g_tree[2][NCHUNK][KTAG][KTAG];

__device__ __forceinline__ unsigned long long packhf(unsigned tag, float v) {
    return ((unsigned long long)tag << 32) | (unsigned long long)__float_as_uint(v);
}
__device__ __forceinline__ float tanh_fast(float x) {
    return 1.f - 2.f / (__expf(2.f * x) + 1.f);
}
__device__ __forceinline__ float sigm_fast(float x) {
    return 1.f / (1.f + __expf(-x));
}

// ---------------- init: seed h0 in all replicas (tag 0), poison other parity ----------------
__global__ void init_kernel(const float* __restrict__ h0) {
    int tid = threadIdx.x;                // 1024 threads
    int dir = tid >> 9, i = tid & 511;
    float v = h0[dir * HID + i];
#pragma unroll
    for (int r = 0; r < NREP; r++) {
        g_hrep[dir][0][r][i] = packhf(0u, v);
        g_hrep[dir][1][r][i] = packhf(0x7fffffffu, 0.f);
    }
}

// ---------------- K1: x_proj = emb(gather) @ w_ih^T + b_ih + b_hh ----------------
__global__ __launch_bounds__(256) void xproj_kernel(
    const int*   __restrict__ sentence,
    const float* __restrict__ embed,
    const float* __restrict__ w_ih_f, const float* __restrict__ b_ih_f, const float* __restrict__ b_hh_f,
    const float* __restrict__ w_ih_b, const float* __restrict__ b_ih_b, const float* __restrict__ b_hh_b)
{
    const int dir = blockIdx.z;
    const float* __restrict__ w_ih = dir ? w_ih_b : w_ih_f;
    const float* __restrict__ bi   = dir ? b_ih_b : b_ih_f;
    const float* __restrict__ bh   = dir ? b_hh_b : b_hh_f;

    const int j0 = blockIdx.x * 64;
    const int t0 = blockIdx.y * 64;

    __shared__ __align__(16) float As[8][64];
    __shared__ __align__(16) float Bs[8][64];
    __shared__ int sidx[64];

    const int tid = threadIdx.x;
    if (tid < 64) {
        int t = t0 + tid;
        sidx[tid] = sentence[dir ? (T_LEN - 1 - t) : t];
    }
    __syncthreads();

    const int tx = tid & 15, ty = tid >> 4;
    const int lr = tid >> 2;
    const int le = (tid & 3) * 2;

    float acc[4][4] = {};

    for (int e0 = 0; e0 < EMBD; e0 += 8) {
        const float* arow = embed + (size_t)sidx[lr] * EMBD;
        const float* brow = w_ih + (size_t)(j0 + lr) * EMBD;
        int e = e0 + le;
        As[le][lr]     = (e     < EMBD) ? arow[e]     : 0.f;
        As[le + 1][lr] = (e + 1 < EMBD) ? arow[e + 1] : 0.f;
        Bs[le][lr]     = (e     < EMBD) ? brow[e]     : 0.f;
        Bs[le + 1][lr] = (e + 1 < EMBD) ? brow[e + 1] : 0.f;
        __syncthreads();
#pragma unroll
        for (int kk = 0; kk < 8; kk++) {
            float4 a = *(const float4*)&As[kk][ty * 4];
            float4 b = *(const float4*)&Bs[kk][tx * 4];
            float av[4] = {a.x, a.y, a.z, a.w};
            float bv[4] = {b.x, b.y, b.z, b.w};
#pragma unroll
            for (int i = 0; i < 4; i++)
#pragma unroll
                for (int j = 0; j < 4; j++)
                    acc[i][j] = fmaf(av[i], bv[j], acc[i][j]);
        }
        __syncthreads();
    }

#pragma unroll
    for (int i = 0; i < 4; i++) {
        int t = t0 + ty * 4 + i;
#pragma unroll
        for (int j = 0; j < 4; j++) {
            int jj = j0 + tx * 4 + j;
            g_xproj[dir][t][jj] = acc[i][j] + bi[jj] + bh[jj];
        }
    }
}

// ---------------- K3: persistent BiLSTM (disjoint dirs, replicated h broadcast) ----------------
// 128 CTAs (64/dir). Warp w owns h-idx = cid*8+w (all 4 gate rows).
// Consumers poll replica (cid & 3) only: 16 CTAs/line -> no LTS slice saturation.
__global__ __launch_bounds__(256, 1) void lstm_kernel(
    const float* __restrict__ w_hh_f,
    const float* __restrict__ w_hh_b,
    const float* __restrict__ c0)
{
    const int dir  = blockIdx.x >> 6;
    const int cid  = blockIdx.x & 63;
    const float* __restrict__ w_hh = dir ? w_hh_b : w_hh_f;

    const int tid  = threadIdx.x;
    const int wid  = tid >> 5;
    const int lane = tid & 31;
    const int hidx = cid * 8 + wid;
    const int rep  = cid & (NREP - 1);

    // weights: w4[g][j] = w_hh[g*512+hidx][j*128 + 4*lane .. +3]
    float4 w4[4][4];
#pragma unroll
    for (int g = 0; g < 4; g++) {
        const float* wr = w_hh + (size_t)(g * HID + hidx) * HID + 4 * lane;
#pragma unroll
        for (int j = 0; j < 4; j++)
            w4[g][j] = *(const float4*)(wr + j * 128);
    }

    __shared__ __align__(16) float h_sh[2][HID];

    float creg = (lane == 0) ? c0[dir * HID + hidx] : 0.f;
    float xp   = (lane < 4) ? g_xproj[dir][0][lane * HID + hidx] : 0.f;

    for (int t = 0; t < T_LEN; t++) {
        const int p = t & 1;
        // --- poll own 2 pairs of h(t) from this CTA's replica, stash to smem ---
        {
            const unsigned long long* pa = g_hrep[dir][p][rep] + 2 * tid;
            const unsigned wanted = (unsigned)t;
            unsigned long long a, b;
            do {
                asm volatile("ld.relaxed.gpu.global.v2.u64 {%0,%1}, [%2];"
                             : "=l"(a), "=l"(b) : "l"(pa) : "memory");
            } while ((unsigned)(a >> 32) != wanted || (unsigned)(b >> 32) != wanted);
            h_sh[p][2 * tid]     = __uint_as_float((unsigned)a);
            h_sh[p][2 * tid + 1] = __uint_as_float((unsigned)b);
        }
        __syncthreads();

        // --- matvec: 16 h values per lane feed all 4 gate rows ---
        const float* hb = h_sh[p] + 4 * lane;
        float4 h0 = *(const float4*)(hb);
        float4 h1 = *(const float4*)(hb + 128);
        float4 h2 = *(const float4*)(hb + 256);
        float4 h3 = *(const float4*)(hb + 384);

        float acc0, acc1, acc2, acc3;
        {
            float4 h[4] = {h0, h1, h2, h3};
            float a[4];
#pragma unroll
            for (int g = 0; g < 4; g++) {
                float s0 = 0.f, s1 = 0.f;
#pragma unroll
                for (int j = 0; j < 4; j++) {
                    s0 = fmaf(w4[g][j].x, h[j].x, s0);
                    s1 = fmaf(w4[g][j].y, h[j].y, s1);
                    s0 = fmaf(w4[g][j].z, h[j].z, s0);
                    s1 = fmaf(w4[g][j].w, h[j].w, s1);
                }
                a[g] = s0 + s1;
            }
            acc0 = a[0]; acc1 = a[1]; acc2 = a[2]; acc3 = a[3];
        }
#pragma unroll
        for (int off = 16; off; off >>= 1) {
            acc0 += __shfl_xor_sync(0xffffffffu, acc0, off);
            acc1 += __shfl_xor_sync(0xffffffffu, acc1, off);
            acc2 += __shfl_xor_sync(0xffffffffu, acc2, off);
            acc3 += __shfl_xor_sync(0xffffffffu, acc3, off);
        }

        // lanes 0..3 apply their gate's nonlinearity in parallel
        float nl = 0.f;
        if (lane < 4) {
            float v = (lane == 0) ? acc0 : (lane == 1) ? acc1
                    : (lane == 2) ? acc2 : acc3;
            v += xp;
            nl = (lane == 2) ? tanh_fast(v) : sigm_fast(v);
        }
        float ff = __shfl_sync(0xffffffffu, nl, 1);
        float tg = __shfl_sync(0xffffffffu, nl, 2);
        float fo = __shfl_sync(0xffffffffu, nl, 3);
        if (lane == 0) {
            creg = ff * creg + nl * tg;          // nl = fi on lane 0
            float hn = fo * tanh_fast(creg);
            unsigned long long pv = packhf((unsigned)(t + 1), hn);
            // publish to all replicas of the next-parity buffer (flights overlap)
            unsigned long long* wp = g_hrep[dir][p ^ 1][0] + hidx;
#pragma unroll
            for (int r = 0; r < NREP; r++)
                asm volatile("st.relaxed.gpu.global.u64 [%0], %1;"
                             :: "l"(wp + r * HPAD), "l"(pv) : "memory");
            g_hs[dir][t][hidx] = hn;
        }
        if (lane < 4 && t + 1 < T_LEN)
            xp = g_xproj[dir][t + 1][lane * HID + hidx];   // prefetch
        // no trailing barrier: next stash targets the other parity buffer.
    }
}

// ---------------- K4: feats[t,k] = [h_f(t), h_b(t)] . W_tag[k] + b_tag[k] ----------------
__global__ __launch_bounds__(256) void feats_kernel(
    const float* __restrict__ W_tag, const float* __restrict__ b_tag)
{
    const int t = blockIdx.x;
    __shared__ float hsm[2 * HID];
    const int tid = threadIdx.x;
    for (int i = tid; i < HID; i += 256) {
        hsm[i]       = g_hs[0][t][i];
        hsm[HID + i] = g_hs[1][T_LEN - 1 - t][i];
    }
    __syncthreads();
    const int wid = tid >> 5, lane = tid & 31;
    for (int k = wid; k < KTAG; k += 8) {
        const float* wrow = W_tag + (size_t)k * (2 * HID);
        float s = 0.f;
#pragma unroll
        for (int m = 0; m < 32; m++)
            s = fmaf(wrow[m * 32 + lane], hsm[m * 32 + lane], s);
#pragma unroll
        for (int off = 16; off; off >>= 1)
            s += __shfl_xor_sync(0xffffffffu, s, off);
        if (lane == 0) g_feats[t][k] = s + b_tag[k];
    }
}

// ---------------- K5a: per-chunk sequential composition (256 warps) ----------------
__global__ __launch_bounds__(32) void crf_chunk_kernel(const float* __restrict__ trans)
{
    const int c = blockIdx.x;
    const int lane = threadIdx.x;
    __shared__ float Tsm[KTAG][KTAG];
    __shared__ float Mbuf[2][KTAG][KTAG];
    __shared__ float fsm[KTAG];

    for (int i = lane; i < KTAG * KTAG; i += 32)
        Tsm[i / KTAG][i % KTAG] = trans[i];
    __syncwarp();

    if (lane < KTAG) fsm[lane] = g_feats[c * CHUNK][lane];
    __syncwarp();
    for (int e = lane; e < KTAG * KTAG; e += 32)
        Mbuf[0][e / KTAG][e % KTAG] = Tsm[e / KTAG][e % KTAG] + fsm[e / KTAG];
    __syncwarp();

    int cur = 0;
    for (int s = 1; s < CHUNK; s++) {
        if (lane < KTAG) fsm[lane] = g_feats[c * CHUNK + s][lane];
        __syncwarp();
        for (int e = lane; e < KTAG * KTAG; e += 32) {
            int j = e / KTAG, i = e % KTAG;
            float v[KTAG], mx = -3.4e38f;
#pragma unroll
            for (int k = 0; k < KTAG; k++) {
                v[k] = Tsm[j][k] + Mbuf[cur][k][i];
                mx = fmaxf(mx, v[k]);
            }
            float sm = 0.f;
#pragma unroll
            for (int k = 0; k < KTAG; k++) sm += __expf(v[k] - mx);
            Mbuf[cur ^ 1][j][i] = fsm[j] + mx + __logf(sm);
        }
        __syncwarp();
        cur ^= 1;
    }
    for (int e = lane; e < KTAG * KTAG; e += 32)
        g_tree[0][c][e / KTAG][e % KTAG] = Mbuf[cur][e / KTAG][e % KTAG];
}

// ---------------- K5b: tree combine. out[b] = in[2b+1] (.) in[2b] ----------------
__global__ __launch_bounds__(32) void crf_combine_kernel(int s)
{
    const int b = blockIdx.x;
    const int lane = threadIdx.x;
    const float (*in)[KTAG][KTAG]  = g_tree[s & 1];
    float (*out)[KTAG][KTAG]       = g_tree[(s & 1) ^ 1];
    __shared__ float Lo[KTAG][KTAG], Hi[KTAG][KTAG];
    for (int i = lane; i < KTAG * KTAG; i += 32) {
        Lo[i / KTAG][i % KTAG] = in[2 * b][i / KTAG][i % KTAG];
        Hi[i / KTAG][i % KTAG] = in[2 * b + 1][i / KTAG][i % KTAG];
    }
    __syncwarp();
    for (int e = lane; e < KTAG * KTAG; e += 32) {
        int j = e / KTAG, i = e % KTAG;
        float v[KTAG], mx = -3.4e38f;
#pragma unroll
        for (int k = 0; k < KTAG; k++) {
            v[k] = Hi[j][k] + Lo[k][i];
            mx = fmaxf(mx, v[k]);
        }
        float sm = 0.f;
#pragma unroll
        for (int k = 0; k < KTAG; k++) sm += __expf(v[k] - mx);
        out[b][j][i] = mx + __logf(sm);
    }
}

// ---------------- K5c: final score = forward - gold ----------------
__global__ void crf_final_kernel(const int* __restrict__ tags,
                                 const float* __restrict__ trans,
                                 float* __restrict__ out)
{
    __shared__ float partial[128];
    const int tid = threadIdx.x;

    float loc = 0.f;
    for (int t = tid; t < T_LEN; t += 128) {
        int tg = tags[t];
        int pv = t ? tags[t - 1] : START_TAG;
        loc += trans[tg * KTAG + pv] + g_feats[t][tg];
    }
    partial[tid] = loc;
    __syncthreads();

    if (tid == 0) {
        float gold = trans[STOP_TAG * KTAG + tags[T_LEN - 1]];
        for (int i = 0; i < 128; i++) gold += partial[i];

        const float (*C)[KTAG] = g_tree[0][0];
        float alpha[KTAG];
        for (int j = 0; j < KTAG; j++) {
            float mx = -3.4e38f, v[KTAG];
            for (int i = 0; i < KTAG; i++) {
                v[i] = C[j][i] + ((i == START_TAG) ? 0.f : NEGV);
                mx = fmaxf(mx, v[i]);
            }
            float sm = 0.f;
            for (int i = 0; i < KTAG; i++) sm += __expf(v[i] - mx);
            alpha[j] = mx + __logf(sm);
        }
        float mx = -3.4e38f;
        for (int j = 0; j < KTAG; j++)
            mx = fmaxf(mx, alpha[j] + trans[STOP_TAG * KTAG + j]);
        float sm = 0.f;
        for (int j = 0; j < KTAG; j++)
            sm += __expf(alpha[j] + trans[STOP_TAG * KTAG + j] - mx);
        out[0] = (mx + __logf(sm)) - gold;
    }
}

// ---------------- launch ----------------
extern "C" void kernel_launch(void* const* d_in, const int* in_sizes, int n_in,
                              void* d_out, int out_size)
{
    const int*   sentence = (const int*)d_in[0];
    const int*   tags     = (const int*)d_in[1];
    const float* embed    = (const float*)d_in[2];
    const float* w_ih_f   = (const float*)d_in[3];
    const float* w_hh_f   = (const float*)d_in[4];
    const float* b_ih_f   = (const float*)d_in[5];
    const float* b_hh_f   = (const float*)d_in[6];
    const float* w_ih_b   = (const float*)d_in[7];
    const float* w_hh_b   = (const float*)d_in[8];
    const float* b_ih_b   = (const float*)d_in[9];
    const float* b_hh_b   = (const float*)d_in[10];
    const float* h0       = (const float*)d_in[11];
    const float* c0       = (const float*)d_in[12];
    const float* W_tag    = (const float*)d_in[13];
    const float* b_tag    = (const float*)d_in[14];
    const float* trans    = (const float*)d_in[15];

    init_kernel<<<1, 1024>>>(h0);

    dim3 g1((4 * HID) / 64, T_LEN / 64, 2);
    xproj_kernel<<<g1, 256>>>(sentence, embed,
                              w_ih_f, b_ih_f, b_hh_f,
                              w_ih_b, b_ih_b, b_hh_b);

    lstm_kernel<<<128, 256>>>(w_hh_f, w_hh_b, c0);

    feats_kernel<<<T_LEN, 256>>>(W_tag, b_tag);

    crf_chunk_kernel<<<NCHUNK, 32>>>(trans);
    for (int s = 0; s < 8; s++)
        crf_combine_kernel<<<(NCHUNK / 2) >> s, 32>>>(s);
    crf_final_kernel<<<1, 128>>>(tags, trans, (float*)d_out);
}

// round 9
// speedup vs baseline: 1.2111x; 1.2111x over previous
#include <cuda_runtime.h>
#include <cuda_bf16.h>
#include <cstdint>
#include <cstddef>

#define T_LEN 4096
#define EMBD  300
#define HID   512
#define KTAG  20
#define START_TAG 18
#define STOP_TAG  19
#define NEGV  (-10000.0f)
#define CHUNK 16
#define NCHUNK (T_LEN / CHUNK)   // 256

// ---------------- scratch (static device globals; no allocation) ----------------
__device__ float              g_xproj[2][T_LEN][4 * HID];  // 64 MB
__device__ float              g_hs[2][T_LEN][HID];         // 16 MB
__device__ float              g_feats[T_LEN][KTAG];
__device__ __align__(16) unsigned long long g_hpair[2][2][HID]; // [dir][parity][h]: {tag|bits}
__device__ float              g_tree[2][NCHUNK][KTAG][KTAG];

__device__ __forceinline__ unsigned long long packhf(unsigned tag, float v) {
    return ((unsigned long long)tag << 32) | (unsigned long long)__float_as_uint(v);
}
__device__ __forceinline__ float tanh_fast(float x) {
    return 1.f - 2.f / (__expf(2.f * x) + 1.f);
}
__device__ __forceinline__ float sigm_fast(float x) {
    return 1.f / (1.f + __expf(-x));
}

// ---------------- init: seed h0 (tag 0); parity-1 gets tag 0 (any tag < 1 blocks) ----------------
__global__ void init_kernel(const float* __restrict__ h0) {
    int tid = threadIdx.x;                // 1024 threads
    int dir = tid >> 9, i = tid & 511;
    g_hpair[dir][0][i] = packhf(0u, h0[dir * HID + i]);
    g_hpair[dir][1][i] = packhf(0u, 0.f);   // tag 0 < first wanted tag (1)
}

// ---------------- K1: x_proj = emb(gather) @ w_ih^T + b_ih + b_hh ----------------
__global__ __launch_bounds__(256) void xproj_kernel(
    const int*   __restrict__ sentence,
    const float* __restrict__ embed,
    const float* __restrict__ w_ih_f, const float* __restrict__ b_ih_f, const float* __restrict__ b_hh_f,
    const float* __restrict__ w_ih_b, const float* __restrict__ b_ih_b, const float* __restrict__ b_hh_b)
{
    const int dir = blockIdx.z;
    const float* __restrict__ w_ih = dir ? w_ih_b : w_ih_f;
    const float* __restrict__ bi   = dir ? b_ih_b : b_ih_f;
    const float* __restrict__ bh   = dir ? b_hh_b : b_hh_f;

    const int j0 = blockIdx.x * 64;
    const int t0 = blockIdx.y * 64;

    __shared__ __align__(16) float As[8][64];
    __shared__ __align__(16) float Bs[8][64];
    __shared__ int sidx[64];

    const int tid = threadIdx.x;
    if (tid < 64) {
        int t = t0 + tid;
        sidx[tid] = sentence[dir ? (T_LEN - 1 - t) : t];
    }
    __syncthreads();

    const int tx = tid & 15, ty = tid >> 4;
    const int lr = tid >> 2;
    const int le = (tid & 3) * 2;

    float acc[4][4] = {};

    for (int e0 = 0; e0 < EMBD; e0 += 8) {
        const float* arow = embed + (size_t)sidx[lr] * EMBD;
        const float* brow = w_ih + (size_t)(j0 + lr) * EMBD;
        int e = e0 + le;
        As[le][lr]     = (e     < EMBD) ? arow[e]     : 0.f;
        As[le + 1][lr] = (e + 1 < EMBD) ? arow[e + 1] : 0.f;
        Bs[le][lr]     = (e     < EMBD) ? brow[e]     : 0.f;
        Bs[le + 1][lr] = (e + 1 < EMBD) ? brow[e + 1] : 0.f;
        __syncthreads();
#pragma unroll
        for (int kk = 0; kk < 8; kk++) {
            float4 a = *(const float4*)&As[kk][ty * 4];
            float4 b = *(const float4*)&Bs[kk][tx * 4];
            float av[4] = {a.x, a.y, a.z, a.w};
            float bv[4] = {b.x, b.y, b.z, b.w};
#pragma unroll
            for (int i = 0; i < 4; i++)
#pragma unroll
                for (int j = 0; j < 4; j++)
                    acc[i][j] = fmaf(av[i], bv[j], acc[i][j]);
        }
        __syncthreads();
    }

#pragma unroll
    for (int i = 0; i < 4; i++) {
        int t = t0 + ty * 4 + i;
#pragma unroll
        for (int j = 0; j < 4; j++) {
            int jj = j0 + tx * 4 + j;
            g_xproj[dir][t][jj] = acc[i][j] + bi[jj] + bh[jj];
        }
    }
}

// ---------------- K3: persistent BiLSTM (32 CTAs/dir, 2 h-indices per warp) ----------------
// 64 CTAs. Warp w of CTA cid owns h-indices h0i=cid*16+2w, h0i+1 (8 gate rows).
// Poll: thread tid checks u64s {2tid, 2tid+1} with MONOTONE tag compare (replay-safe).
__global__ __launch_bounds__(256, 1) void lstm_kernel(
    const float* __restrict__ w_hh_f,
    const float* __restrict__ w_hh_b,
    const float* __restrict__ c0)
{
    const int dir  = blockIdx.x >> 5;
    const int cid  = blockIdx.x & 31;
    const float* __restrict__ w_hh = dir ? w_hh_b : w_hh_f;

    const int tid  = threadIdx.x;
    const int wid  = tid >> 5;
    const int lane = tid & 31;
    const int h0i  = cid * 16 + 2 * wid;

    // weights: 8 rows (j = gate + 4*(h offset)), 16 k-values per lane
    float4 w4[8][4];
#pragma unroll
    for (int j = 0; j < 8; j++) {
        const int row = (j & 3) * HID + h0i + (j >> 2);
        const float* wr = w_hh + (size_t)row * HID + 4 * lane;
#pragma unroll
        for (int q = 0; q < 4; q++)
            w4[j][q] = *(const float4*)(wr + q * 128);
    }

    __shared__ __align__(16) float h_sh[2][HID];

    float creg = (lane == 0) ? c0[dir * HID + h0i]
               : (lane == 4) ? c0[dir * HID + h0i + 1] : 0.f;
    float xp = (lane < 8)
             ? g_xproj[dir][0][(lane & 3) * HID + h0i + (lane >> 2)] : 0.f;

    for (int t = 0; t < T_LEN; t++) {
        const int p = t & 1;
        // --- poll own 2 pairs of h(t), monotone tag check, stash to smem ---
        {
            const unsigned long long* pa = g_hpair[dir][p] + 2 * tid;
            const unsigned wanted = (unsigned)t;
            unsigned long long a, b;
            do {
                asm volatile("ld.relaxed.gpu.global.v2.u64 {%0,%1}, [%2];"
                             : "=l"(a), "=l"(b) : "l"(pa) : "memory");
            } while ((unsigned)(a >> 32) < wanted || (unsigned)(b >> 32) < wanted);
            h_sh[p][2 * tid]     = __uint_as_float((unsigned)a);
            h_sh[p][2 * tid + 1] = __uint_as_float((unsigned)b);
        }
        __syncthreads();

        // --- matvec: 16 h values per lane feed all 8 rows ---
        const float* hb = h_sh[p] + 4 * lane;
        float4 hq[4];
#pragma unroll
        for (int q = 0; q < 4; q++) hq[q] = *(const float4*)(hb + q * 128);

        float accv[8];
#pragma unroll
        for (int j = 0; j < 8; j++) {
            float s0 = 0.f, s1 = 0.f;
#pragma unroll
            for (int q = 0; q < 4; q++) {
                s0 = fmaf(w4[j][q].x, hq[q].x, s0);
                s1 = fmaf(w4[j][q].y, hq[q].y, s1);
                s0 = fmaf(w4[j][q].z, hq[q].z, s0);
                s1 = fmaf(w4[j][q].w, hq[q].w, s1);
            }
            accv[j] = s0 + s1;
        }
#pragma unroll
        for (int off = 16; off; off >>= 1) {
#pragma unroll
            for (int j = 0; j < 8; j++)
                accv[j] += __shfl_xor_sync(0xffffffffu, accv[j], off);
        }

        // lane j (0..7) applies nonlinearity for row j
        float v = accv[0];
#pragma unroll
        for (int j = 1; j < 8; j++) v = (lane == j) ? accv[j] : v;
        v += xp;
        float nl = ((lane & 3) == 2) ? tanh_fast(v) : sigm_fast(v);

        const int base = lane & 4;   // gate group base for lanes 0..7
        float ff = __shfl_sync(0xffffffffu, nl, base + 1);
        float tg = __shfl_sync(0xffffffffu, nl, base + 2);
        float fo = __shfl_sync(0xffffffffu, nl, base + 3);

        // lanes 0 and 4 hold cells for h0i and h0i+1
        float hn = 0.f;
        if (lane == 0 || lane == 4) {
            creg = ff * creg + nl * tg;          // nl = fi on lanes 0,4
            hn = fo * tanh_fast(creg);
        }
        float hn1 = __shfl_sync(0xffffffffu, hn, 4);
        if (lane == 0) {
            unsigned tg1 = (unsigned)(t + 1);
            unsigned long long pv0 = packhf(tg1, hn);
            unsigned long long pv1 = packhf(tg1, hn1);
            asm volatile("st.relaxed.gpu.global.v2.u64 [%0], {%1,%2};"
                         :: "l"(g_hpair[dir][p ^ 1] + h0i), "l"(pv0), "l"(pv1)
                         : "memory");
            *(float2*)&g_hs[dir][t][h0i] = make_float2(hn, hn1);
        }
        if (lane < 8 && t + 1 < T_LEN)
            xp = g_xproj[dir][t + 1][(lane & 3) * HID + h0i + (lane >> 2)];
        // no trailing barrier: next stash targets the other parity buffer.
    }
}

// ---------------- K4: feats[t,k] = [h_f(t), h_b(t)] . W_tag[k] + b_tag[k] ----------------
__global__ __launch_bounds__(256) void feats_kernel(
    const float* __restrict__ W_tag, const float* __restrict__ b_tag)
{
    const int t = blockIdx.x;
    __shared__ float hsm[2 * HID];
    const int tid = threadIdx.x;
    for (int i = tid; i < HID; i += 256) {
        hsm[i]       = g_hs[0][t][i];
        hsm[HID + i] = g_hs[1][T_LEN - 1 - t][i];
    }
    __syncthreads();
    const int wid = tid >> 5, lane = tid & 31;
    for (int k = wid; k < KTAG; k += 8) {
        const float* wrow = W_tag + (size_t)k * (2 * HID);
        float s = 0.f;
#pragma unroll
        for (int m = 0; m < 32; m++)
            s = fmaf(wrow[m * 32 + lane], hsm[m * 32 + lane], s);
#pragma unroll
        for (int off = 16; off; off >>= 1)
            s += __shfl_xor_sync(0xffffffffu, s, off);
        if (lane == 0) g_feats[t][k] = s + b_tag[k];
    }
}

// ---------------- K5a: per-chunk sequential composition (256 warps) ----------------
__global__ __launch_bounds__(32) void crf_chunk_kernel(const float* __restrict__ trans)
{
    const int c = blockIdx.x;
    const int lane = threadIdx.x;
    __shared__ float Tsm[KTAG][KTAG];
    __shared__ float Mbuf[2][KTAG][KTAG];
    __shared__ float fsm[KTAG];

    for (int i = lane; i < KTAG * KTAG; i += 32)
        Tsm[i / KTAG][i % KTAG] = trans[i];
    __syncwarp();

    if (lane < KTAG) fsm[lane] = g_feats[c * CHUNK][lane];
    __syncwarp();
    for (int e = lane; e < KTAG * KTAG; e += 32)
        Mbuf[0][e / KTAG][e % KTAG] = Tsm[e / KTAG][e % KTAG] + fsm[e / KTAG];
    __syncwarp();

    int cur = 0;
    for (int s = 1; s < CHUNK; s++) {
        if (lane < KTAG) fsm[lane] = g_feats[c * CHUNK + s][lane];
        __syncwarp();
        for (int e = lane; e < KTAG * KTAG; e += 32) {
            int j = e / KTAG, i = e % KTAG;
            float v[KTAG], mx = -3.4e38f;
#pragma unroll
            for (int k = 0; k < KTAG; k++) {
                v[k] = Tsm[j][k] + Mbuf[cur][k][i];
                mx = fmaxf(mx, v[k]);
            }
            float sm = 0.f;
#pragma unroll
            for (int k = 0; k < KTAG; k++) sm += __expf(v[k] - mx);
            Mbuf[cur ^ 1][j][i] = fsm[j] + mx + __logf(sm);
        }
        __syncwarp();
        cur ^= 1;
    }
    for (int e = lane; e < KTAG * KTAG; e += 32)
        g_tree[0][c][e / KTAG][e % KTAG] = Mbuf[cur][e / KTAG][e % KTAG];
}

// ---------------- K5b: tree combine. out[b] = in[2b+1] (.) in[2b] ----------------
__global__ __launch_bounds__(32) void crf_combine_kernel(int s)
{
    const int b = blockIdx.x;
    const int lane = threadIdx.x;
    const float (*in)[KTAG][KTAG]  = g_tree[s & 1];
    float (*out)[KTAG][KTAG]       = g_tree[(s & 1) ^ 1];
    __shared__ float Lo[KTAG][KTAG], Hi[KTAG][KTAG];
    for (int i = lane; i < KTAG * KTAG; i += 32) {
        Lo[i / KTAG][i % KTAG] = in[2 * b][i / KTAG][i % KTAG];
        Hi[i / KTAG][i % KTAG] = in[2 * b + 1][i / KTAG][i % KTAG];
    }
    __syncwarp();
    for (int e = lane; e < KTAG * KTAG; e += 32) {
        int j = e / KTAG, i = e % KTAG;
        float v[KTAG], mx = -3.4e38f;
#pragma unroll
        for (int k = 0; k < KTAG; k++) {
            v[k] = Hi[j][k] + Lo[k][i];
            mx = fmaxf(mx, v[k]);
        }
        float sm = 0.f;
#pragma unroll
        for (int k = 0; k < KTAG; k++) sm += __expf(v[k] - mx);
        out[b][j][i] = mx + __logf(sm);
    }
}

// ---------------- K5c: final score = forward - gold ----------------
__global__ void crf_final_kernel(const int* __restrict__ tags,
                                 const float* __restrict__ trans,
                                 float* __restrict__ out)
{
    __shared__ float partial[128];
    const int tid = threadIdx.x;

    float loc = 0.f;
    for (int t = tid; t < T_LEN; t += 128) {
        int tg = tags[t];
        int pv = t ? tags[t - 1] : START_TAG;
        loc += trans[tg * KTAG + pv] + g_feats[t][tg];
    }
    partial[tid] = loc;
    __syncthreads();

    if (tid == 0) {
        float gold = trans[STOP_TAG * KTAG + tags[T_LEN - 1]];
        for (int i = 0; i < 128; i++) gold += partial[i];

        const float (*C)[KTAG] = g_tree[0][0];
        float alpha[KTAG];
        for (int j = 0; j < KTAG; j++) {
            float mx = -3.4e38f, v[KTAG];
            for (int i = 0; i < KTAG; i++) {
                v[i] = C[j][i] + ((i == START_TAG) ? 0.f : NEGV);
                mx = fmaxf(mx, v[i]);
            }
            float sm = 0.f;
            for (int i = 0; i < KTAG; i++) sm += __expf(v[i] - mx);
            alpha[j] = mx + __logf(sm);
        }
        float mx = -3.4e38f;
        for (int j = 0; j < KTAG; j++)
            mx = fmaxf(mx, alpha[j] + trans[STOP_TAG * KTAG + j]);
        float sm = 0.f;
        for (int j = 0; j < KTAG; j++)
            sm += __expf(alpha[j] + trans[STOP_TAG * KTAG + j] - mx);
        out[0] = (mx + __logf(sm)) - gold;
    }
}

// ---------------- launch ----------------
extern "C" void kernel_launch(void* const* d_in, const int* in_sizes, int n_in,
                              void* d_out, int out_size)
{
    const int*   sentence = (const int*)d_in[0];
    const int*   tags     = (const int*)d_in[1];
    const float* embed    = (const float*)d_in[2];
    const float* w_ih_f   = (const float*)d_in[3];
    const float* w_hh_f   = (const float*)d_in[4];
    const float* b_ih_f   = (const float*)d_in[5];
    const float* b_hh_f   = (const float*)d_in[6];
    const float* w_ih_b   = (const float*)d_in[7];
    const float* w_hh_b   = (const float*)d_in[8];
    const float* b_ih_b   = (const float*)d_in[9];
    const float* b_hh_b   = (const float*)d_in[10];
    const float* h0       = (const float*)d_in[11];
    const float* c0       = (const float*)d_in[12];
    const float* W_tag    = (const float*)d_in[13];
    const float* b_tag    = (const float*)d_in[14];
    const float* trans    = (const float*)d_in[15];

    init_kernel<<<1, 1024>>>(h0);

    dim3 g1((4 * HID) / 64, T_LEN / 64, 2);
    xproj_kernel<<<g1, 256>>>(sentence, embed,
                              w_ih_f, b_ih_f, b_hh_f,
                              w_ih_b, b_ih_b, b_hh_b);

    lstm_kernel<<<64, 256>>>(w_hh_f, w_hh_b, c0);

    feats_kernel<<<T_LEN, 256>>>(W_tag, b_tag);

    crf_chunk_kernel<<<NCHUNK, 32>>>(trans);
    for (int s = 0; s < 8; s++)
        crf_combine_kernel<<<(NCHUNK / 2) >> s, 32>>>(s);
    crf_final_kernel<<<1, 128>>>(tags, trans, (float*)d_out);
}

// round 11
// speedup vs baseline: 1.2216x; 1.0086x over previous
#include <cuda_runtime.h>
#include <cuda_bf16.h>
#include <cstdint>
#include <cstddef>

#define T_LEN 4096
#define EMBD  300
#define HID   512
#define KTAG  20
#define START_TAG 18
#define STOP_TAG  19
#define NEGV  (-10000.0f)
#define CHUNK 16
#define NCHUNK (T_LEN / CHUNK)   // 256

// ---------------- scratch (static device globals; no allocation) ----------------
__device__ float              g_xproj[2][T_LEN][4 * HID];  // 64 MB
__device__ float              g_hs[2][T_LEN][HID];         // 16 MB
__device__ float              g_feats[T_LEN][KTAG];
__device__ __align__(16) unsigned long long g_hpair[2][2][HID]; // [dir][parity][h]: {tag|bits}
__device__ float              g_tree[2][NCHUNK][KTAG][KTAG];

__device__ __forceinline__ unsigned long long packhf(unsigned tag, float v) {
    return ((unsigned long long)tag << 32) | (unsigned long long)__float_as_uint(v);
}
__device__ __forceinline__ float tanh_ap(float x) {
    float y;
    asm("tanh.approx.f32 %0, %1;" : "=f"(y) : "f"(x));
    return y;
}
__device__ __forceinline__ float sigm_ap(float x) {
    return fmaf(0.5f, tanh_ap(0.5f * x), 0.5f);
}

// ---------------- init: seed h0 (tag 0); parity-1 gets tag 0 (any tag < 1 blocks) ----------------
__global__ void init_kernel(const float* __restrict__ h0) {
    int tid = threadIdx.x;                // 1024 threads
    int dir = tid >> 9, i = tid & 511;
    g_hpair[dir][0][i] = packhf(0u, h0[dir * HID + i]);
    g_hpair[dir][1][i] = packhf(0u, 0.f);   // tag 0 < first wanted tag (1)
}

// dummy launch: shifts the fixed "-s 5 -c 1" ncu capture window onto lstm_kernel
__global__ void dummy_kernel() {}

// ---------------- K1: x_proj = emb(gather) @ w_ih^T + b_ih + b_hh ----------------
__global__ __launch_bounds__(256) void xproj_kernel(
    const int*   __restrict__ sentence,
    const float* __restrict__ embed,
    const float* __restrict__ w_ih_f, const float* __restrict__ b_ih_f, const float* __restrict__ b_hh_f,
    const float* __restrict__ w_ih_b, const float* __restrict__ b_ih_b, const float* __restrict__ b_hh_b)
{
    const int dir = blockIdx.z;
    const float* __restrict__ w_ih = dir ? w_ih_b : w_ih_f;
    const float* __restrict__ bi   = dir ? b_ih_b : b_ih_f;
    const float* __restrict__ bh   = dir ? b_hh_b : b_hh_f;

    const int j0 = blockIdx.x * 64;
    const int t0 = blockIdx.y * 64;

    __shared__ __align__(16) float As[8][64];
    __shared__ __align__(16) float Bs[8][64];
    __shared__ int sidx[64];

    const int tid = threadIdx.x;
    if (tid < 64) {
        int t = t0 + tid;
        sidx[tid] = sentence[dir ? (T_LEN - 1 - t) : t];
    }
    __syncthreads();

    const int tx = tid & 15, ty = tid >> 4;
    const int lr = tid >> 2;
    const int le = (tid & 3) * 2;

    float acc[4][4] = {};

    for (int e0 = 0; e0 < EMBD; e0 += 8) {
        const float* arow = embed + (size_t)sidx[lr] * EMBD;
        const float* brow = w_ih + (size_t)(j0 + lr) * EMBD;
        int e = e0 + le;
        As[le][lr]     = (e     < EMBD) ? arow[e]     : 0.f;
        As[le + 1][lr] = (e + 1 < EMBD) ? arow[e + 1] : 0.f;
        Bs[le][lr]     = (e     < EMBD) ? brow[e]     : 0.f;
        Bs[le + 1][lr] = (e + 1 < EMBD) ? brow[e + 1] : 0.f;
        __syncthreads();
#pragma unroll
        for (int kk = 0; kk < 8; kk++) {
            float4 a = *(const float4*)&As[kk][ty * 4];
            float4 b = *(const float4*)&Bs[kk][tx * 4];
            float av[4] = {a.x, a.y, a.z, a.w};
            float bv[4] = {b.x, b.y, b.z, b.w};
#pragma unroll
            for (int i = 0; i < 4; i++)
#pragma unroll
                for (int j = 0; j < 4; j++)
                    acc[i][j] = fmaf(av[i], bv[j], acc[i][j]);
        }
        __syncthreads();
    }

#pragma unroll
    for (int i = 0; i < 4; i++) {
        int t = t0 + ty * 4 + i;
#pragma unroll
        for (int j = 0; j < 4; j++) {
            int jj = j0 + tx * 4 + j;
            g_xproj[dir][t][jj] = acc[i][j] + bi[jj] + bh[jj];
        }
    }
}

// ---------------- K3: persistent BiLSTM (32 CTAs/dir, 2 h-indices per warp) ----------------
// Exact R9 structure (proven passing); only the nonlinearities use tanh.approx.
__global__ __launch_bounds__(256, 1) void lstm_kernel(
    const float* __restrict__ w_hh_f,
    const float* __restrict__ w_hh_b,
    const float* __restrict__ c0)
{
    const int dir  = blockIdx.x >> 5;
    const int cid  = blockIdx.x & 31;
    const float* __restrict__ w_hh = dir ? w_hh_b : w_hh_f;

    const int tid  = threadIdx.x;
    const int wid  = tid >> 5;
    const int lane = tid & 31;
    const int h0i  = cid * 16 + 2 * wid;

    // weights: 8 rows (j = gate + 4*(h offset)), 16 k-values per lane
    float4 w4[8][4];
#pragma unroll
    for (int j = 0; j < 8; j++) {
        const int row = (j & 3) * HID + h0i + (j >> 2);
        const float* wr = w_hh + (size_t)row * HID + 4 * lane;
#pragma unroll
        for (int q = 0; q < 4; q++)
            w4[j][q] = *(const float4*)(wr + q * 128);
    }

    __shared__ __align__(16) float h_sh[2][HID];

    float creg = (lane == 0) ? c0[dir * HID + h0i]
               : (lane == 4) ? c0[dir * HID + h0i + 1] : 0.f;
    float xp = (lane < 8)
             ? g_xproj[dir][0][(lane & 3) * HID + h0i + (lane >> 2)] : 0.f;

    for (int t = 0; t < T_LEN; t++) {
        const int p = t & 1;
        // --- poll own 2 pairs of h(t), monotone tag check, stash to smem ---
        {
            const unsigned long long* pa = g_hpair[dir][p] + 2 * tid;
            const unsigned wanted = (unsigned)t;
            unsigned long long a, b;
            do {
                asm volatile("ld.relaxed.gpu.global.v2.u64 {%0,%1}, [%2];"
                             : "=l"(a), "=l"(b) : "l"(pa) : "memory");
            } while ((unsigned)(a >> 32) < wanted || (unsigned)(b >> 32) < wanted);
            h_sh[p][2 * tid]     = __uint_as_float((unsigned)a);
            h_sh[p][2 * tid + 1] = __uint_as_float((unsigned)b);
        }
        __syncthreads();

        // --- matvec: 16 h values per lane feed all 8 rows ---
        const float* hb = h_sh[p] + 4 * lane;
        float4 hq[4];
#pragma unroll
        for (int q = 0; q < 4; q++) hq[q] = *(const float4*)(hb + q * 128);

        float accv[8];
#pragma unroll
        for (int j = 0; j < 8; j++) {
            float s0 = 0.f, s1 = 0.f;
#pragma unroll
            for (int q = 0; q < 4; q++) {
                s0 = fmaf(w4[j][q].x, hq[q].x, s0);
                s1 = fmaf(w4[j][q].y, hq[q].y, s1);
                s0 = fmaf(w4[j][q].z, hq[q].z, s0);
                s1 = fmaf(w4[j][q].w, hq[q].w, s1);
            }
            accv[j] = s0 + s1;
        }
#pragma unroll
        for (int off = 16; off; off >>= 1) {
#pragma unroll
            for (int j = 0; j < 8; j++)
                accv[j] += __shfl_xor_sync(0xffffffffu, accv[j], off);
        }

        // lane j (0..7) applies nonlinearity for row j
        float v = accv[0];
#pragma unroll
        for (int j = 1; j < 8; j++) v = (lane == j) ? accv[j] : v;
        v += xp;
        float nl = ((lane & 3) == 2) ? tanh_ap(v) : sigm_ap(v);

        const int base = lane & 4;   // gate group base for lanes 0..7
        float ff = __shfl_sync(0xffffffffu, nl, base + 1);
        float tg = __shfl_sync(0xffffffffu, nl, base + 2);
        float fo = __shfl_sync(0xffffffffu, nl, base + 3);

        // lanes 0 and 4 hold cells for h0i and h0i+1
        float hn = 0.f;
        if (lane == 0 || lane == 4) {
            creg = ff * creg + nl * tg;          // nl = fi on lanes 0,4
            hn = fo * tanh_ap(creg);
        }
        float hn1 = __shfl_sync(0xffffffffu, hn, 4);
        if (lane == 0) {
            unsigned tg1 = (unsigned)(t + 1);
            unsigned long long pv0 = packhf(tg1, hn);
            unsigned long long pv1 = packhf(tg1, hn1);
            asm volatile("st.relaxed.gpu.global.v2.u64 [%0], {%1,%2};"
                         :: "l"(g_hpair[dir][p ^ 1] + h0i), "l"(pv0), "l"(pv1)
                         : "memory");
            *(float2*)&g_hs[dir][t][h0i] = make_float2(hn, hn1);
        }
        if (lane < 8 && t + 1 < T_LEN)
            xp = g_xproj[dir][t + 1][(lane & 3) * HID + h0i + (lane >> 2)];
        // no trailing barrier: next stash targets the other parity buffer.
    }
}

// ---------------- K4: feats[t,k] = [h_f(t), h_b(t)] . W_tag[k] + b_tag[k] ----------------
__global__ __launch_bounds__(256) void feats_kernel(
    const float* __restrict__ W_tag, const float* __restrict__ b_tag)
{
    const int t = blockIdx.x;
    __shared__ float hsm[2 * HID];
    const int tid = threadIdx.x;
    for (int i = tid; i < HID; i += 256) {
        hsm[i]       = g_hs[0][t][i];
        hsm[HID + i] = g_hs[1][T_LEN - 1 - t][i];
    }
    __syncthreads();
    const int wid = tid >> 5, lane = tid & 31;
    for (int k = wid; k < KTAG; k += 8) {
        const float* wrow = W_tag + (size_t)k * (2 * HID);
        float s = 0.f;
#pragma unroll
        for (int m = 0; m < 32; m++)
            s = fmaf(wrow[m * 32 + lane], hsm[m * 32 + lane], s);
#pragma unroll
        for (int off = 16; off; off >>= 1)
            s += __shfl_xor_sync(0xffffffffu, s, off);
        if (lane == 0) g_feats[t][k] = s + b_tag[k];
    }
}

// ---------------- K5a: per-chunk sequential composition (256 warps) ----------------
__global__ __launch_bounds__(32) void crf_chunk_kernel(const float* __restrict__ trans)
{
    const int c = blockIdx.x;
    const int lane = threadIdx.x;
    __shared__ float Tsm[KTAG][KTAG];
    __shared__ float Mbuf[2][KTAG][KTAG];
    __shared__ float fsm[KTAG];

    for (int i = lane; i < KTAG * KTAG; i += 32)
        Tsm[i / KTAG][i % KTAG] = trans[i];
    __syncwarp();

    if (lane < KTAG) fsm[lane] = g_feats[c * CHUNK][lane];
    __syncwarp();
    for (int e = lane; e < KTAG * KTAG; e += 32)
        Mbuf[0][e / KTAG][e % KTAG] = Tsm[e / KTAG][e % KTAG] + fsm[e / KTAG];
    __syncwarp();

    int cur = 0;
    for (int s = 1; s < CHUNK; s++) {
        if (lane < KTAG) fsm[lane] = g_feats[c * CHUNK + s][lane];
        __syncwarp();
        for (int e = lane; e < KTAG * KTAG; e += 32) {
            int j = e / KTAG, i = e % KTAG;
            float v[KTAG], mx = -3.4e38f;
#pragma unroll
            for (int k = 0; k < KTAG; k++) {
                v[k] = Tsm[j][k] + Mbuf[cur][k][i];
                mx = fmaxf(mx, v[k]);
            }
            float sm = 0.f;
#pragma unroll
            for (int k = 0; k < KTAG; k++) sm += __expf(v[k] - mx);
            Mbuf[cur ^ 1][j][i] = fsm[j] + mx + __logf(sm);
        }
        __syncwarp();
        cur ^= 1;
    }
    for (int e = lane; e < KTAG * KTAG; e += 32)
        g_tree[0][c][e / KTAG][e % KTAG] = Mbuf[cur][e / KTAG][e % KTAG];
}

// ---------------- K5b: tree combine. out[b] = in[2b+1] (.) in[2b] ----------------
__global__ __launch_bounds__(32) void crf_combine_kernel(int s)
{
    const int b = blockIdx.x;
    const int lane = threadIdx.x;
    const float (*in)[KTAG][KTAG]  = g_tree[s & 1];
    float (*out)[KTAG][KTAG]       = g_tree[(s & 1) ^ 1];
    __shared__ float Lo[KTAG][KTAG], Hi[KTAG][KTAG];
    for (int i = lane; i < KTAG * KTAG; i += 32) {
        Lo[i / KTAG][i % KTAG] = in[2 * b][i / KTAG][i % KTAG];
        Hi[i / KTAG][i % KTAG] = in[2 * b + 1][i / KTAG][i % KTAG];
    }
    __syncwarp();
    for (int e = lane; e < KTAG * KTAG; e += 32) {
        int j = e / KTAG, i = e % KTAG;
        float v[KTAG], mx = -3.4e38f;
#pragma unroll
        for (int k = 0; k < KTAG; k++) {
            v[k] = Hi[j][k] + Lo[k][i];
            mx = fmaxf(mx, v[k]);
        }
        float sm = 0.f;
#pragma unroll
        for (int k = 0; k < KTAG; k++) sm += __expf(v[k] - mx);
        out[b][j][i] = mx + __logf(sm);
    }
}

// ---------------- K5c: final score = forward - gold ----------------
__global__ void crf_final_kernel(const int* __restrict__ tags,
                                 const float* __restrict__ trans,
                                 float* __restrict__ out)
{
    __shared__ float partial[128];
    const int tid = threadIdx.x;

    float loc = 0.f;
    for (int t = tid; t < T_LEN; t += 128) {
        int tg = tags[t];
        int pv = t ? tags[t - 1] : START_TAG;
        loc += trans[tg * KTAG + pv] + g_feats[t][tg];
    }
    partial[tid] = loc;
    __syncthreads();

    if (tid == 0) {
        float gold = trans[STOP_TAG * KTAG + tags[T_LEN - 1]];
        for (int i = 0; i < 128; i++) gold += partial[i];

        const float (*C)[KTAG] = g_tree[0][0];
        float alpha[KTAG];
        for (int j = 0; j < KTAG; j++) {
            float mx = -3.4e38f, v[KTAG];
            for (int i = 0; i < KTAG; i++) {
                v[i] = C[j][i] + ((i == START_TAG) ? 0.f : NEGV);
                mx = fmaxf(mx, v[i]);
            }
            float sm = 0.f;
            for (int i = 0; i < KTAG; i++) sm += __expf(v[i] - mx);
            alpha[j] = mx + __logf(sm);
        }
        float mx = -3.4e38f;
        for (int j = 0; j < KTAG; j++)
            mx = fmaxf(mx, alpha[j] + trans[STOP_TAG * KTAG + j]);
        float sm = 0.f;
        for (int j = 0; j < KTAG; j++)
            sm += __expf(alpha[j] + trans[STOP_TAG * KTAG + j] - mx);
        out[0] = (mx + __logf(sm)) - gold;
    }
}

// ---------------- launch ----------------
extern "C" void kernel_launch(void* const* d_in, const int* in_sizes, int n_in,
                              void* d_out, int out_size)
{
    const int*   sentence = (const int*)d_in[0];
    const int*   tags     = (const int*)d_in[1];
    const float* embed    = (const float*)d_in[2];
    const float* w_ih_f   = (const float*)d_in[3];
    const float* w_hh_f   = (const float*)d_in[4];
    const float* b_ih_f   = (const float*)d_in[5];
    const float* b_hh_f   = (const float*)d_in[6];
    const float* w_ih_b   = (const float*)d_in[7];
    const float* w_hh_b   = (const float*)d_in[8];
    const float* b_ih_b   = (const float*)d_in[9];
    const float* b_hh_b   = (const float*)d_in[10];
    const float* h0       = (const float*)d_in[11];
    const float* c0       = (const float*)d_in[12];
    const float* W_tag    = (const float*)d_in[13];
    const float* b_tag    = (const float*)d_in[14];
    const float* trans    = (const float*)d_in[15];

    init_kernel<<<1, 1024>>>(h0);

    dim3 g1((4 * HID) / 64, T_LEN / 64, 2);
    xproj_kernel<<<g1, 256>>>(sentence, embed,
                              w_ih_f, b_ih_f, b_hh_f,
                              w_ih_b, b_ih_b, b_hh_b);

    dummy_kernel<<<1, 32>>>();   // shifts ncu capture (-s 5) onto lstm_kernel

    lstm_kernel<<<64, 256>>>(w_hh_f, w_hh_b, c0);

    feats_kernel<<<T_LEN, 256>>>(W_tag, b_tag);

    crf_chunk_kernel<<<NCHUNK, 32>>>(trans);
    for (int s = 0; s < 8; s++)
        crf_combine_kernel<<<(NCHUNK / 2) >> s, 32>>>(s);
    crf_final_kernel<<<1, 128>>>(tags, trans, (float*)d_out);
}